// round 13
// baseline (speedup 1.0000x reference)
#include <cuda_runtime.h>
#include <cuda_fp16.h>
#include <math.h>
#include <stdint.h>

#define NTOK 8192
#define DDIM 1024
#define HDIM 4096
#define NEXP 8
#define CAP  2048
#define NENT (2*NTOK)

#define STAGES 3
#define STAGE_BYTES 32768          // A 16KB (128m x 64k) + B 16KB (64k x 128n), fp16
#define DSMEM_BYTES (STAGES*STAGE_BYTES + 1024)

#define CONV_UNITS 512
#define WELEMS ((size_t)NEXP*DDIM*HDIM)
#define WQUADS (WELEMS/4)
#define QPB    (WQUADS/CONV_UNITS)           // 16384 float4 per unit
#define GATE_CONV 256
#define POS_CONV_BLOCKS 64                   // 1024-thread blocks, 4 units each

// ---------------- scratch (device globals; no allocation allowed) ----------------
__device__ __half g_xh[(size_t)NTOK*DDIM];         // 16 MB fp16 tokens
__device__ __half g_h[(size_t)NEXP*CAP*HDIM];      // 128 MB
__device__ float  g_y[(size_t)NEXP*CAP*DDIM];      // 64 MB
__device__ __half g_w1h[WELEMS];                   // 64 MB
__device__ __half g_w2h[WELEMS];                   // 64 MB
__device__ int    g_eid[NENT];
__device__ float  g_gv[NENT];
__device__ int    g_pos[NENT];
__device__ int    g_inv[NEXP*CAP];                 // slot -> token (0 if empty)

// ---------------- helpers ----------------
__device__ __forceinline__ uint32_t s2u(const void* p) {
    uint32_t a;
    asm("{ .reg .u64 t; cvta.to.shared.u64 t, %1; cvt.u32.u64 %0, t; }" : "=r"(a) : "l"(p));
    return a;
}
__device__ __forceinline__ void cpasync16(uint32_t dst, const void* src) {
    asm volatile("cp.async.cg.shared.global [%0], [%1], 16;" :: "r"(dst), "l"(src));
}
__device__ __forceinline__ void cp_commit() { asm volatile("cp.async.commit_group;" ::: "memory"); }
template<int N> __device__ __forceinline__ void cp_wait() {
    asm volatile("cp.async.wait_group %0;" :: "n"(N) : "memory");
}
__device__ __forceinline__ void ldsm4(uint32_t* d, uint32_t addr) {
    asm volatile("ldmatrix.sync.aligned.m8n8.x4.shared.b16 {%0,%1,%2,%3}, [%4];"
        : "=r"(d[0]), "=r"(d[1]), "=r"(d[2]), "=r"(d[3]) : "r"(addr));
}
__device__ __forceinline__ void ldsm4t(uint32_t* d, uint32_t addr) {
    asm volatile("ldmatrix.sync.aligned.m8n8.x4.trans.shared.b16 {%0,%1,%2,%3}, [%4];"
        : "=r"(d[0]), "=r"(d[1]), "=r"(d[2]), "=r"(d[3]) : "r"(addr));
}
__device__ __forceinline__ void mma16816(float* d, const uint32_t* a, const uint32_t* b) {
    asm volatile(
        "mma.sync.aligned.m16n8k16.row.col.f32.f16.f16.f32 "
        "{%0,%1,%2,%3}, {%4,%5,%6,%7}, {%8,%9}, {%0,%1,%2,%3};"
        : "+f"(d[0]), "+f"(d[1]), "+f"(d[2]), "+f"(d[3])
        : "r"(a[0]), "r"(a[1]), "r"(a[2]), "r"(a[3]), "r"(b[0]), "r"(b[1]));
}
__device__ __forceinline__ float gelu_exact(float v) {
    return 0.5f * v * (1.f + erff(v * 0.70710678118654752f));
}
__device__ __forceinline__ void conv_units(const float* __restrict__ W,
                                           __half* __restrict__ Wh,
                                           int u0, int units, int tid, int nthr) {
    size_t base = (size_t)u0 * QPB;
    size_t count = (size_t)units * QPB;
    for (size_t j = tid; j < count; j += nthr) {
        size_t i = base + j;
        const float4 v = ((const float4*)W)[i];
        __half2* o = (__half2*)Wh + i * 2;
        o[0] = __floats2half2_rn(v.x, v.y);
        o[1] = __floats2half2_rn(v.z, v.w);
    }
}

// ---------------- gate (+ fp16 token conversion + w1 convert units [0,GATE_CONV)) --------
__global__ void gate_kernel(const float* __restrict__ x, const float* __restrict__ wg,
                            const float* __restrict__ w1) {
    if (blockIdx.x >= NTOK/8) {
        conv_units(w1, g_w1h, blockIdx.x - NTOK/8, 1, threadIdx.x, 256);
        return;
    }
    __shared__ float wsh[NEXP*DDIM];
    int tid = threadIdx.x;
    for (int i = tid; i < NEXP*DDIM; i += 256) {
        int d = i / NEXP, e = i % NEXP;
        wsh[e*DDIM + d] = wg[i];
    }
    __syncthreads();
    int warp = tid >> 5, lane = tid & 31;
    int n = blockIdx.x * 8 + warp;
    const float* xr = x + (size_t)n * DDIM;
    __half2* xo = (__half2*)(g_xh + (size_t)n * DDIM);
    float acc[NEXP];
#pragma unroll
    for (int e = 0; e < NEXP; e++) acc[e] = 0.f;
    for (int d = lane * 2; d < DDIM; d += 64) {
        float2 xv = *(const float2*)(xr + d);
        xo[d >> 1] = __floats2half2_rn(xv.x, xv.y);
#pragma unroll
        for (int e = 0; e < NEXP; e++)
            acc[e] += xv.x * wsh[e*DDIM + d] + xv.y * wsh[e*DDIM + d + 1];
    }
#pragma unroll
    for (int e = 0; e < NEXP; e++) {
#pragma unroll
        for (int off = 16; off; off >>= 1)
            acc[e] += __shfl_xor_sync(0xffffffffu, acc[e], off);
    }
    if (lane == 0) {
        float l0 = -1e30f; int i0 = 0;
#pragma unroll
        for (int e = 0; e < NEXP; e++) if (acc[e] > l0) { l0 = acc[e]; i0 = e; }
        float l1 = -1e30f; int i1 = 0;
#pragma unroll
        for (int e = 0; e < NEXP; e++) if (e != i0 && acc[e] > l1) { l1 = acc[e]; i1 = e; }
        float r  = expf(l1 - l0);
        float g0 = 1.f / (1.f + r);
        g_eid[n]        = i0;
        g_eid[NTOK + n] = i1;
        g_gv[n]         = g0;
        g_gv[NTOK + n]  = 1.f - g0;
    }
}

// ---------------- GShard positions + inverse map (block 0) + w1 convert ----------------
__global__ void pos_kernel(const float* __restrict__ w1) {
    if (blockIdx.x > 0) {
        conv_units(w1, g_w1h, GATE_CONV + (blockIdx.x - 1) * 4, 4, threadIdx.x, 1024);
        return;
    }
    __shared__ int cnt[1024][NEXP];
    int t = threadIdx.x;
    int base = t * 16;
#pragma unroll
    for (int j = 0; j < 16; j++) g_inv[base + j] = 0;   // NEXP*CAP == 16384
#pragma unroll
    for (int e = 0; e < NEXP; e++) cnt[t][e] = 0;
    for (int j = 0; j < 16; j++) cnt[t][g_eid[base + j]]++;
    __syncthreads();
    if (t < 256) {
        int w = t >> 5, lane = t & 31;
        int s = 0;
        for (int j = 0; j < 32; j++) s += cnt[lane*32 + j][w];
        int incl = s;
#pragma unroll
        for (int off = 1; off < 32; off <<= 1) {
            int v = __shfl_up_sync(0xffffffffu, incl, off);
            if (lane >= off) incl += v;
        }
        int run = incl - s;
        for (int j = 0; j < 32; j++) {
            int v = cnt[lane*32 + j][w];
            cnt[lane*32 + j][w] = run;
            run += v;
        }
    }
    __syncthreads();
    for (int j = 0; j < 16; j++) {
        int i = base + j;
        int e = g_eid[i];
        int p = cnt[t][e]++;
        if (p < CAP) {
            g_pos[i] = p;
            g_inv[e*CAP + p] = i & (NTOK - 1);   // token index
        } else {
            g_pos[i] = -1;
            g_gv[i]  = 0.f;
        }
    }
}

// ---------------- fp16 mma GEMM ----------------
// CTA 128x128, BK=64, 3-stage cp.async, 8 warps (4m x 2n), warp tile 32x64.
// GATHER=1 (gemm1): A rows gathered from g_xh via g_inv (no dispatch buffer);
//                   grid.z==NEXP blocks convert w2; GELU+fp16 store.
// GATHER=0 (gemm2): contiguous A (g_h); fp32 store.
template<int KDIM, int NDIM, bool GATHER, typename OutT>
__global__ void __launch_bounds__(256, 2)
gemm_mma(const __half* __restrict__ Abase, const __half* __restrict__ Bbase,
         const float* __restrict__ biasb, OutT* __restrict__ Cbase,
         const float* __restrict__ Wsrc, __half* __restrict__ Wdst) {
    extern __shared__ char dynsm[];
    __shared__ int tok_s[128];
    int tid = threadIdx.x;

    if (GATHER && blockIdx.z == NEXP) {
        int bid = blockIdx.y * gridDim.x + blockIdx.x;   // 0..511
        conv_units(Wsrc, Wdst, bid, 1, tid, 256);
        return;
    }

    uint32_t sbase = (s2u(dynsm) + 1023u) & ~1023u;
    int lane = tid & 31, warp = tid >> 5;
    int e = blockIdx.z;
    int bm = blockIdx.y * 128, bn = blockIdx.x * 128;
    const __half* B = Bbase + (size_t)e * KDIM * NDIM + bn;
    const float* bias = biasb + (size_t)e * NDIM + bn;

    const __half* A;
    if (GATHER) {
        if (tid < 128) tok_s[tid] = g_inv[e*CAP + bm + tid];
        __syncthreads();
        A = Abase;                                    // g_xh; per-row offset via tok_s
    } else {
        A = Abase + (size_t)e * CAP * KDIM + (size_t)bm * KDIM;
    }

    constexpr int KT = KDIM / 64;

    int wm = (warp >> 1) * 32;
    int wn = (warp & 1) * 64;
    int r8 = lane & 7, t4 = lane >> 3;

    float acc[2][8][4];
#pragma unroll
    for (int mi = 0; mi < 2; mi++)
#pragma unroll
        for (int ni = 0; ni < 8; ni++)
#pragma unroll
            for (int q = 0; q < 4; q++) acc[mi][ni][q] = 0.f;

    auto load_stage = [&](int kt) {
        uint32_t sa = sbase + (uint32_t)(kt % STAGES) * STAGE_BYTES;
        uint32_t sb = sa + 16384;
        const __half* Bp = B + (size_t)(kt * 64) * NDIM;
#pragma unroll
        for (int i = 0; i < 4; i++) {
            int idx = i * 256 + tid;
            int row = idx >> 3, c = idx & 7;
            const __half* src;
            if (GATHER)
                src = A + (size_t)tok_s[row] * KDIM + kt * 64 + c * 8;
            else
                src = A + (size_t)row * KDIM + kt * 64 + c * 8;
            cpasync16(sa + (uint32_t)(row * 128 + ((c ^ (row & 7)) << 4)), src);
        }
#pragma unroll
        for (int i = 0; i < 4; i++) {
            int idx = i * 256 + tid;
            int row = idx >> 4, c = idx & 15;
            cpasync16(sb + (uint32_t)(row * 256 + ((c ^ (row & 7)) << 4)),
                      Bp + (size_t)row * NDIM + c * 8);
        }
    };

#pragma unroll
    for (int kt = 0; kt < STAGES - 1; kt++) { load_stage(kt); cp_commit(); }

    for (int kt = 0; kt < KT; kt++) {
        cp_wait<STAGES - 2>();
        __syncthreads();

        int ktp = kt + STAGES - 1;
        if (ktp < KT) load_stage(ktp);
        cp_commit();

        uint32_t sA = sbase + (uint32_t)(kt % STAGES) * STAGE_BYTES;
        uint32_t sB = sA + 16384;
#pragma unroll
        for (int ks4 = 0; ks4 < 4; ks4++) {
            int kc = ks4 * 2;
            uint32_t a[2][4], b[8][2];
#pragma unroll
            for (int mi = 0; mi < 2; mi++) {
                int row = wm + mi * 16 + (t4 & 1) * 8 + r8;
                int cc  = kc + (t4 >> 1);
                ldsm4(a[mi], sA + (uint32_t)(row * 128 + ((cc ^ (row & 7)) << 4)));
            }
#pragma unroll
            for (int nj = 0; nj < 4; nj++) {
                int krow = ks4 * 16 + (lane & 15);
                int c    = ((wn + nj * 16) >> 3) + (lane >> 4);
                uint32_t q[4];
                ldsm4t(q, sB + (uint32_t)(krow * 256 + ((c ^ (krow & 7)) << 4)));
                b[2*nj][0]   = q[0]; b[2*nj][1]   = q[1];
                b[2*nj+1][0] = q[2]; b[2*nj+1][1] = q[3];
            }
#pragma unroll
            for (int mi = 0; mi < 2; mi++)
#pragma unroll
                for (int ni = 0; ni < 8; ni++)
                    mma16816(acc[mi][ni], a[mi], b[ni]);
        }
    }

    // epilogue
    int grp = lane >> 2, tig = lane & 3;
    OutT* Ce = Cbase + (size_t)e * CAP * NDIM;
#pragma unroll
    for (int mi = 0; mi < 2; mi++) {
#pragma unroll
        for (int ni = 0; ni < 8; ni++) {
            int row = bm + wm + mi * 16 + grp;
            int col = bn + wn + ni * 8 + tig * 2;
            float b0  = bias[wn + ni * 8 + tig * 2];
            float b1v = bias[wn + ni * 8 + tig * 2 + 1];
            float v0 = acc[mi][ni][0] + b0;
            float v1 = acc[mi][ni][1] + b1v;
            float v2 = acc[mi][ni][2] + b0;
            float v3 = acc[mi][ni][3] + b1v;
            if (GATHER) {          // gemm1: GELU + fp16 h
                v0 = gelu_exact(v0); v1 = gelu_exact(v1);
                v2 = gelu_exact(v2); v3 = gelu_exact(v3);
            }
            if (sizeof(OutT) == 2) {
                *(__half2*)((__half*)Ce + (size_t)row * NDIM + col) = __floats2half2_rn(v0, v1);
                *(__half2*)((__half*)Ce + (size_t)(row + 8) * NDIM + col) = __floats2half2_rn(v2, v3);
            } else {
                *(float2*)((float*)Ce + (size_t)row * NDIM + col) = make_float2(v0, v1);
                *(float2*)((float*)Ce + (size_t)(row + 8) * NDIM + col) = make_float2(v2, v3);
            }
        }
    }
}

// ---------------- combine (fp32 gather + gate-weighted sum) ----------------
__global__ void combine_kernel(float* __restrict__ out) {
    int n = blockIdx.x;
    int t = threadIdx.x;
    float4 acc = make_float4(0.f, 0.f, 0.f, 0.f);
#pragma unroll
    for (int kk = 0; kk < 2; kk++) {
        int i = kk * NTOK + n;
        int p = g_pos[i];
        if (p >= 0) {
            float g = g_gv[i];
            const float4 v = *((const float4*)(g_y + (size_t)(g_eid[i]*CAP + p) * DDIM) + t);
            acc.x += g * v.x; acc.y += g * v.y;
            acc.z += g * v.z; acc.w += g * v.w;
        }
    }
    ((float4*)out)[(size_t)n * 256 + t] = acc;
}

// ---------------- launch ----------------
extern "C" void kernel_launch(void* const* d_in, const int* in_sizes, int n_in,
                              void* d_out, int out_size) {
    const float* x  = (const float*)d_in[0];
    const float* wg = (const float*)d_in[1];
    const float* w1 = (const float*)d_in[2];
    const float* b1 = (const float*)d_in[3];
    const float* w2 = (const float*)d_in[4];
    const float* b2 = (const float*)d_in[5];
    float* out = (float*)d_out;

    static int attr_done = 0;
    if (!attr_done) {
        cudaFuncSetAttribute(gemm_mma<DDIM, HDIM, true,  __half>,
                             cudaFuncAttributeMaxDynamicSharedMemorySize, DSMEM_BYTES);
        cudaFuncSetAttribute(gemm_mma<HDIM, DDIM, false, float>,
                             cudaFuncAttributeMaxDynamicSharedMemorySize, DSMEM_BYTES);
        attr_done = 1;
    }

    __half* xh;   cudaGetSymbolAddress((void**)&xh,   g_xh);
    __half* w1h;  cudaGetSymbolAddress((void**)&w1h,  g_w1h);
    __half* w2h;  cudaGetSymbolAddress((void**)&w2h,  g_w2h);
    __half* hbuf; cudaGetSymbolAddress((void**)&hbuf, g_h);
    float*  ybuf; cudaGetSymbolAddress((void**)&ybuf, g_y);

    gate_kernel<<<NTOK/8 + GATE_CONV, 256>>>(x, wg, w1);
    pos_kernel<<<1 + POS_CONV_BLOCKS, 1024>>>(w1);
    gemm_mma<DDIM, HDIM, true, __half>
        <<<dim3(HDIM/128, CAP/128, NEXP + 1), 256, DSMEM_BYTES>>>(
        xh, w1h, b1, hbuf, w2, w2h);
    gemm_mma<HDIM, DDIM, false, float>
        <<<dim3(DDIM/128, CAP/128, NEXP), 256, DSMEM_BYTES>>>(
        hbuf, w2h, b2, ybuf, nullptr, nullptr);
    combine_kernel<<<NTOK, 256>>>(out);
}

// round 14
// speedup vs baseline: 1.0461x; 1.0461x over previous
#include <cuda_runtime.h>
#include <cuda_fp16.h>
#include <math.h>
#include <stdint.h>

#define NTOK 8192
#define DDIM 1024
#define HDIM 4096
#define NEXP 8
#define CAP  2048
#define NENT (2*NTOK)

#define STAGES 3
#define STAGE_BYTES 32768          // A 16KB (128m x 64k) + B 16KB (64k x 128n), fp16
#define DSMEM_BYTES (STAGES*STAGE_BYTES + 1024)

#define CONV_UNITS 512
#define WELEMS ((size_t)NEXP*DDIM*HDIM)
#define WQUADS (WELEMS/4)                    // 8,388,608 float4
#define QPB    (WQUADS/CONV_UNITS)           // 16384 float4 per unit
#define GATE_CONV 256
#define POS_CONV_BLOCKS 64                   // 1024-thread blocks, 4 units each

// ---------------- scratch (device globals; no allocation allowed) ----------------
__device__ __half g_disp[(size_t)NEXP*CAP*DDIM];   // 32 MB
__device__ __half g_h[(size_t)NEXP*CAP*HDIM];      // 128 MB
__device__ float  g_y[(size_t)NEXP*CAP*DDIM];      // 64 MB
__device__ __half g_w1h[WELEMS];                   // 64 MB
__device__ __half g_w2h[WELEMS];                   // 64 MB
__device__ int    g_eid[NENT];
__device__ float  g_gv[NENT];
__device__ int    g_pos[NENT];

// ---------------- helpers ----------------
__device__ __forceinline__ uint32_t s2u(const void* p) {
    uint32_t a;
    asm("{ .reg .u64 t; cvta.to.shared.u64 t, %1; cvt.u32.u64 %0, t; }" : "=r"(a) : "l"(p));
    return a;
}
__device__ __forceinline__ void cpasync16(uint32_t dst, const void* src) {
    asm volatile("cp.async.cg.shared.global [%0], [%1], 16;" :: "r"(dst), "l"(src));
}
__device__ __forceinline__ void cp_commit() { asm volatile("cp.async.commit_group;" ::: "memory"); }
template<int N> __device__ __forceinline__ void cp_wait() {
    asm volatile("cp.async.wait_group %0;" :: "n"(N) : "memory");
}
__device__ __forceinline__ void ldsm4(uint32_t* d, uint32_t addr) {
    asm volatile("ldmatrix.sync.aligned.m8n8.x4.shared.b16 {%0,%1,%2,%3}, [%4];"
        : "=r"(d[0]), "=r"(d[1]), "=r"(d[2]), "=r"(d[3]) : "r"(addr));
}
__device__ __forceinline__ void ldsm4t(uint32_t* d, uint32_t addr) {
    asm volatile("ldmatrix.sync.aligned.m8n8.x4.trans.shared.b16 {%0,%1,%2,%3}, [%4];"
        : "=r"(d[0]), "=r"(d[1]), "=r"(d[2]), "=r"(d[3]) : "r"(addr));
}
__device__ __forceinline__ void mma16816(float* d, const uint32_t* a, const uint32_t* b) {
    asm volatile(
        "mma.sync.aligned.m16n8k16.row.col.f32.f16.f16.f32 "
        "{%0,%1,%2,%3}, {%4,%5,%6,%7}, {%8,%9}, {%0,%1,%2,%3};"
        : "+f"(d[0]), "+f"(d[1]), "+f"(d[2]), "+f"(d[3])
        : "r"(a[0]), "r"(a[1]), "r"(a[2]), "r"(a[3]), "r"(b[0]), "r"(b[1]));
}
__device__ __forceinline__ float gelu_exact(float v) {
    return 0.5f * v * (1.f + erff(v * 0.70710678118654752f));
}
__device__ __forceinline__ void conv_units(const float* __restrict__ W,
                                           __half* __restrict__ Wh,
                                           int u0, int units, int tid, int nthr) {
    size_t base = (size_t)u0 * QPB;
    size_t count = (size_t)units * QPB;
    for (size_t j = tid; j < count; j += nthr) {
        size_t i = base + j;
        const float4 v = ((const float4*)W)[i];
        __half2* o = (__half2*)Wh + i * 2;
        o[0] = __floats2half2_rn(v.x, v.y);
        o[1] = __floats2half2_rn(v.z, v.w);
    }
}

// ---------------- gate (+ w1 convert units [0,GATE_CONV)) ----------------
__global__ void gate_kernel(const float* __restrict__ x, const float* __restrict__ wg,
                            const float* __restrict__ w1) {
    if (blockIdx.x >= NTOK/8) {
        conv_units(w1, g_w1h, blockIdx.x - NTOK/8, 1, threadIdx.x, 256);
        return;
    }
    __shared__ float wsh[NEXP*DDIM];
    int tid = threadIdx.x;
    for (int i = tid; i < NEXP*DDIM; i += 256) {
        int d = i / NEXP, e = i % NEXP;
        wsh[e*DDIM + d] = wg[i];
    }
    __syncthreads();
    int warp = tid >> 5, lane = tid & 31;
    int n = blockIdx.x * 8 + warp;
    const float* xr = x + (size_t)n * DDIM;
    float acc[NEXP];
#pragma unroll
    for (int e = 0; e < NEXP; e++) acc[e] = 0.f;
    for (int d = lane; d < DDIM; d += 32) {
        float xv = xr[d];
#pragma unroll
        for (int e = 0; e < NEXP; e++) acc[e] += xv * wsh[e*DDIM + d];
    }
#pragma unroll
    for (int e = 0; e < NEXP; e++) {
#pragma unroll
        for (int off = 16; off; off >>= 1)
            acc[e] += __shfl_xor_sync(0xffffffffu, acc[e], off);
    }
    if (lane == 0) {
        float l0 = -1e30f; int i0 = 0;
#pragma unroll
        for (int e = 0; e < NEXP; e++) if (acc[e] > l0) { l0 = acc[e]; i0 = e; }
        float l1 = -1e30f; int i1 = 0;
#pragma unroll
        for (int e = 0; e < NEXP; e++) if (e != i0 && acc[e] > l1) { l1 = acc[e]; i1 = e; }
        float r  = expf(l1 - l0);
        float g0 = 1.f / (1.f + r);
        g_eid[n]        = i0;
        g_eid[NTOK + n] = i1;
        g_gv[n]         = g0;
        g_gv[NTOK + n]  = 1.f - g0;
    }
}

// ---------------- GShard capacity positions (block 0) + w1 convert [GATE_CONV,512) --------
__global__ void pos_kernel(const float* __restrict__ w1) {
    if (blockIdx.x > 0) {
        conv_units(w1, g_w1h, GATE_CONV + (blockIdx.x - 1) * 4, 4, threadIdx.x, 1024);
        return;
    }
    __shared__ int cnt[1024][NEXP];
    int t = threadIdx.x;
    int base = t * 16;
#pragma unroll
    for (int e = 0; e < NEXP; e++) cnt[t][e] = 0;
    for (int j = 0; j < 16; j++) cnt[t][g_eid[base + j]]++;
    __syncthreads();
    if (t < 256) {
        int w = t >> 5, lane = t & 31;
        int s = 0;
        for (int j = 0; j < 32; j++) s += cnt[lane*32 + j][w];
        int incl = s;
#pragma unroll
        for (int off = 1; off < 32; off <<= 1) {
            int v = __shfl_up_sync(0xffffffffu, incl, off);
            if (lane >= off) incl += v;
        }
        int run = incl - s;
        for (int j = 0; j < 32; j++) {
            int v = cnt[lane*32 + j][w];
            cnt[lane*32 + j][w] = run;
            run += v;
        }
    }
    __syncthreads();
    for (int j = 0; j < 16; j++) {
        int i = base + j;
        int e = g_eid[i];
        int p = cnt[t][e]++;
        if (p < CAP) {
            g_pos[i] = p;
        } else {
            g_pos[i] = -1;
            g_gv[i]  = 0.f;
        }
    }
}

// ---------------- dispatch scatter (f32 -> fp16) ----------------
__global__ void dispatch_kernel(const float* __restrict__ x) {
    int i = blockIdx.x;
    int p = g_pos[i];
    if (p < 0) return;
    int e = g_eid[i];
    int n = i & (NTOK - 1);
    const float4 v = ((const float4*)(x + (size_t)n * DDIM))[threadIdx.x];
    __half2* dst = (__half2*)(g_disp + (size_t)(e*CAP + p) * DDIM) + threadIdx.x * 2;
    dst[0] = __floats2half2_rn(v.x, v.y);
    dst[1] = __floats2half2_rn(v.z, v.w);
}

// ---------------- fp16 mma GEMM ----------------
// CTA 128x128, BK=64, 3-stage cp.async, 8 warps (4m x 2n), warp tile 32x64.
// gemm1 (DO_GELU=1, CONV=1): grid.z==NEXP blocks convert w2 (needed only by gemm2).
template<int KDIM, int NDIM, bool DO_GELU, bool CONV, typename OutT>
__global__ void __launch_bounds__(256, 2)
gemm_mma(const __half* __restrict__ Abase, const __half* __restrict__ Bbase,
         const float* __restrict__ biasb, OutT* __restrict__ Cbase,
         const float* __restrict__ Wsrc, __half* __restrict__ Wdst) {
    extern __shared__ char dynsm[];
    int tid = threadIdx.x;

    if (CONV && blockIdx.z == NEXP) {
        int bid = blockIdx.y * gridDim.x + blockIdx.x;   // 0..511
        conv_units(Wsrc, Wdst, bid, 1, tid, 256);
        return;
    }

    uint32_t sbase = (s2u(dynsm) + 1023u) & ~1023u;
    int lane = tid & 31, warp = tid >> 5;
    int e = blockIdx.z;
    int bm = blockIdx.y * 128, bn = blockIdx.x * 128;
    const __half* A = Abase + (size_t)e * CAP * KDIM + (size_t)bm * KDIM;
    const __half* B = Bbase + (size_t)e * KDIM * NDIM + bn;
    const float* bias = biasb + (size_t)e * NDIM + bn;

    constexpr int KT = KDIM / 64;

    int wm = (warp >> 1) * 32;
    int wn = (warp & 1) * 64;
    int r8 = lane & 7, t4 = lane >> 3;

    float acc[2][8][4];
#pragma unroll
    for (int mi = 0; mi < 2; mi++)
#pragma unroll
        for (int ni = 0; ni < 8; ni++)
#pragma unroll
            for (int q = 0; q < 4; q++) acc[mi][ni][q] = 0.f;

    auto load_stage = [&](int kt) {
        uint32_t sa = sbase + (uint32_t)(kt % STAGES) * STAGE_BYTES;
        uint32_t sb = sa + 16384;
        const __half* Ap = A + kt * 64;
        const __half* Bp = B + (size_t)(kt * 64) * NDIM;
#pragma unroll
        for (int i = 0; i < 4; i++) {
            int idx = i * 256 + tid;
            int row = idx >> 3, c = idx & 7;
            cpasync16(sa + (uint32_t)(row * 128 + ((c ^ (row & 7)) << 4)),
                      Ap + (size_t)row * KDIM + c * 8);
        }
#pragma unroll
        for (int i = 0; i < 4; i++) {
            int idx = i * 256 + tid;
            int row = idx >> 4, c = idx & 15;
            cpasync16(sb + (uint32_t)(row * 256 + ((c ^ (row & 7)) << 4)),
                      Bp + (size_t)row * NDIM + c * 8);
        }
    };

#pragma unroll
    for (int kt = 0; kt < STAGES - 1; kt++) { load_stage(kt); cp_commit(); }

    for (int kt = 0; kt < KT; kt++) {
        cp_wait<STAGES - 2>();
        __syncthreads();

        int ktp = kt + STAGES - 1;
        if (ktp < KT) load_stage(ktp);
        cp_commit();

        uint32_t sA = sbase + (uint32_t)(kt % STAGES) * STAGE_BYTES;
        uint32_t sB = sA + 16384;
#pragma unroll
        for (int ks4 = 0; ks4 < 4; ks4++) {
            int kc = ks4 * 2;
            uint32_t a[2][4], b[8][2];
#pragma unroll
            for (int mi = 0; mi < 2; mi++) {
                int row = wm + mi * 16 + (t4 & 1) * 8 + r8;
                int cc  = kc + (t4 >> 1);
                ldsm4(a[mi], sA + (uint32_t)(row * 128 + ((cc ^ (row & 7)) << 4)));
            }
#pragma unroll
            for (int nj = 0; nj < 4; nj++) {
                int krow = ks4 * 16 + (lane & 15);
                int c    = ((wn + nj * 16) >> 3) + (lane >> 4);
                uint32_t q[4];
                ldsm4t(q, sB + (uint32_t)(krow * 256 + ((c ^ (krow & 7)) << 4)));
                b[2*nj][0]   = q[0]; b[2*nj][1]   = q[1];
                b[2*nj+1][0] = q[2]; b[2*nj+1][1] = q[3];
            }
#pragma unroll
            for (int mi = 0; mi < 2; mi++)
#pragma unroll
                for (int ni = 0; ni < 8; ni++)
                    mma16816(acc[mi][ni], a[mi], b[ni]);
        }
    }

    // epilogue
    int grp = lane >> 2, tig = lane & 3;
    OutT* Ce = Cbase + (size_t)e * CAP * NDIM;
#pragma unroll
    for (int mi = 0; mi < 2; mi++) {
#pragma unroll
        for (int ni = 0; ni < 8; ni++) {
            int row = bm + wm + mi * 16 + grp;
            int col = bn + wn + ni * 8 + tig * 2;
            float b0  = bias[wn + ni * 8 + tig * 2];
            float b1v = bias[wn + ni * 8 + tig * 2 + 1];
            float v0 = acc[mi][ni][0] + b0;
            float v1 = acc[mi][ni][1] + b1v;
            float v2 = acc[mi][ni][2] + b0;
            float v3 = acc[mi][ni][3] + b1v;
            if (DO_GELU) {
                v0 = gelu_exact(v0); v1 = gelu_exact(v1);
                v2 = gelu_exact(v2); v3 = gelu_exact(v3);
            }
            if (sizeof(OutT) == 2) {
                *(__half2*)((__half*)Ce + (size_t)row * NDIM + col) = __floats2half2_rn(v0, v1);
                *(__half2*)((__half*)Ce + (size_t)(row + 8) * NDIM + col) = __floats2half2_rn(v2, v3);
            } else {
                *(float2*)((float*)Ce + (size_t)row * NDIM + col) = make_float2(v0, v1);
                *(float2*)((float*)Ce + (size_t)(row + 8) * NDIM + col) = make_float2(v2, v3);
            }
        }
    }
}

// ---------------- combine (gather + gate-weighted sum) ----------------
__global__ void combine_kernel(float* __restrict__ out) {
    int n = blockIdx.x;
    int t = threadIdx.x;
    float4 acc = make_float4(0.f, 0.f, 0.f, 0.f);
#pragma unroll
    for (int kk = 0; kk < 2; kk++) {
        int i = kk * NTOK + n;
        int p = g_pos[i];
        if (p >= 0) {
            float g = g_gv[i];
            const float4 v = *((const float4*)(g_y + (size_t)(g_eid[i]*CAP + p) * DDIM) + t);
            acc.x += g * v.x; acc.y += g * v.y;
            acc.z += g * v.z; acc.w += g * v.w;
        }
    }
    ((float4*)out)[(size_t)n * 256 + t] = acc;
}

// ---------------- launch ----------------
extern "C" void kernel_launch(void* const* d_in, const int* in_sizes, int n_in,
                              void* d_out, int out_size) {
    const float* x  = (const float*)d_in[0];
    const float* wg = (const float*)d_in[1];
    const float* w1 = (const float*)d_in[2];
    const float* b1 = (const float*)d_in[3];
    const float* w2 = (const float*)d_in[4];
    const float* b2 = (const float*)d_in[5];
    float* out = (float*)d_out;

    static int attr_done = 0;
    if (!attr_done) {
        cudaFuncSetAttribute(gemm_mma<DDIM, HDIM, true,  true,  __half>,
                             cudaFuncAttributeMaxDynamicSharedMemorySize, DSMEM_BYTES);
        cudaFuncSetAttribute(gemm_mma<HDIM, DDIM, false, false, float>,
                             cudaFuncAttributeMaxDynamicSharedMemorySize, DSMEM_BYTES);
        attr_done = 1;
    }

    __half* w1h;  cudaGetSymbolAddress((void**)&w1h,  g_w1h);
    __half* w2h;  cudaGetSymbolAddress((void**)&w2h,  g_w2h);
    __half* disp; cudaGetSymbolAddress((void**)&disp, g_disp);
    __half* hbuf; cudaGetSymbolAddress((void**)&hbuf, g_h);
    float*  ybuf; cudaGetSymbolAddress((void**)&ybuf, g_y);

    // w1 convert rides along gate (256 units) and pos (256 units);
    // w2 convert rides along gemm1 (z == NEXP).
    gate_kernel<<<NTOK/8 + GATE_CONV, 256>>>(x, wg, w1);
    pos_kernel<<<1 + POS_CONV_BLOCKS, 1024>>>(w1);
    dispatch_kernel<<<NENT, 256>>>(x);
    gemm_mma<DDIM, HDIM, true, true, __half>
        <<<dim3(HDIM/128, CAP/128, NEXP + 1), 256, DSMEM_BYTES>>>(
        disp, w1h, b1, hbuf, w2, w2h);
    gemm_mma<HDIM, DDIM, false, false, float>
        <<<dim3(DDIM/128, CAP/128, NEXP), 256, DSMEM_BYTES>>>(
        hbuf, w2h, b2, ybuf, nullptr, nullptr);
    combine_kernel<<<NTOK, 256>>>(out);
}

// round 15
// speedup vs baseline: 1.0512x; 1.0048x over previous
#include <cuda_runtime.h>
#include <cuda_fp16.h>
#include <math.h>
#include <stdint.h>

#define NTOK 8192
#define DDIM 1024
#define HDIM 4096
#define NEXP 8
#define CAP  2048
#define NENT (2*NTOK)

#define STAGES 3
#define STAGE_BYTES 32768          // A 16KB (128m x 64k) + B 16KB (64k x 128n), fp16
#define DSMEM_BYTES (STAGES*STAGE_BYTES + 1024)

#define CONV_UNITS 512
#define WELEMS ((size_t)NEXP*DDIM*HDIM)
#define WQUADS (WELEMS/4)                    // 8,388,608 float4
#define QPB    (WQUADS/CONV_UNITS)           // 16384 float4 per unit
#define GATE_CONV 256
#define POS_CONV_BLOCKS 64                   // 1024-thread blocks, 4 units each

#define G1_TILES_PER_E 512                   // (HDIM/128)*(CAP/128) = 32*16
#define G2_TILES_PER_E 128                   // (DDIM/128)*(CAP/128) = 8*16
#define G1_BLOCKS (NEXP*G1_TILES_PER_E)      // 4096
#define G2_BLOCKS (NEXP*G2_TILES_PER_E)      // 1024
#define FUSED_BLOCKS (CONV_UNITS + G1_BLOCKS + G2_BLOCKS)   // 5632

// ---------------- scratch (device globals; no allocation allowed) ----------------
__device__ __half g_disp[(size_t)NEXP*CAP*DDIM];   // 32 MB
__device__ __half g_h[(size_t)NEXP*CAP*HDIM];      // 128 MB
__device__ float  g_y[(size_t)NEXP*CAP*DDIM];      // 64 MB
__device__ __half g_w1h[WELEMS];                   // 64 MB
__device__ __half g_w2h[WELEMS];                   // 64 MB
__device__ int    g_eid[NENT];
__device__ float  g_gv[NENT];
__device__ int    g_pos[NENT];
__device__ int    g_cnt[NEXP];                     // gemm1 tiles done per expert
__device__ int    g_convcnt;                       // w2 conv units done

// ---------------- helpers ----------------
__device__ __forceinline__ uint32_t s2u(const void* p) {
    uint32_t a;
    asm("{ .reg .u64 t; cvta.to.shared.u64 t, %1; cvt.u32.u64 %0, t; }" : "=r"(a) : "l"(p));
    return a;
}
__device__ __forceinline__ void cpasync16(uint32_t dst, const void* src) {
    asm volatile("cp.async.cg.shared.global [%0], [%1], 16;" :: "r"(dst), "l"(src));
}
__device__ __forceinline__ void cp_commit() { asm volatile("cp.async.commit_group;" ::: "memory"); }
template<int N> __device__ __forceinline__ void cp_wait() {
    asm volatile("cp.async.wait_group %0;" :: "n"(N) : "memory");
}
__device__ __forceinline__ void ldsm4(uint32_t* d, uint32_t addr) {
    asm volatile("ldmatrix.sync.aligned.m8n8.x4.shared.b16 {%0,%1,%2,%3}, [%4];"
        : "=r"(d[0]), "=r"(d[1]), "=r"(d[2]), "=r"(d[3]) : "r"(addr));
}
__device__ __forceinline__ void ldsm4t(uint32_t* d, uint32_t addr) {
    asm volatile("ldmatrix.sync.aligned.m8n8.x4.trans.shared.b16 {%0,%1,%2,%3}, [%4];"
        : "=r"(d[0]), "=r"(d[1]), "=r"(d[2]), "=r"(d[3]) : "r"(addr));
}
__device__ __forceinline__ void mma16816(float* d, const uint32_t* a, const uint32_t* b) {
    asm volatile(
        "mma.sync.aligned.m16n8k16.row.col.f32.f16.f16.f32 "
        "{%0,%1,%2,%3}, {%4,%5,%6,%7}, {%8,%9}, {%0,%1,%2,%3};"
        : "+f"(d[0]), "+f"(d[1]), "+f"(d[2]), "+f"(d[3])
        : "r"(a[0]), "r"(a[1]), "r"(a[2]), "r"(a[3]), "r"(b[0]), "r"(b[1]));
}
__device__ __forceinline__ float gelu_exact(float v) {
    return 0.5f * v * (1.f + erff(v * 0.70710678118654752f));
}
__device__ __forceinline__ void conv_units(const float* __restrict__ W,
                                           __half* __restrict__ Wh,
                                           int u0, int units, int tid, int nthr) {
    size_t base = (size_t)u0 * QPB;
    size_t count = (size_t)units * QPB;
    for (size_t j = tid; j < count; j += nthr) {
        size_t i = base + j;
        const float4 v = ((const float4*)W)[i];
        __half2* o = (__half2*)Wh + i * 2;
        o[0] = __floats2half2_rn(v.x, v.y);
        o[1] = __floats2half2_rn(v.z, v.w);
    }
}

// ---------------- gate (+ w1 convert units [0,GATE_CONV)) ----------------
__global__ void gate_kernel(const float* __restrict__ x, const float* __restrict__ wg,
                            const float* __restrict__ w1) {
    if (blockIdx.x >= NTOK/8) {
        conv_units(w1, g_w1h, blockIdx.x - NTOK/8, 1, threadIdx.x, 256);
        return;
    }
    __shared__ float wsh[NEXP*DDIM];
    int tid = threadIdx.x;
    for (int i = tid; i < NEXP*DDIM; i += 256) {
        int d = i / NEXP, e = i % NEXP;
        wsh[e*DDIM + d] = wg[i];
    }
    __syncthreads();
    int warp = tid >> 5, lane = tid & 31;
    int n = blockIdx.x * 8 + warp;
    const float* xr = x + (size_t)n * DDIM;
    float acc[NEXP];
#pragma unroll
    for (int e = 0; e < NEXP; e++) acc[e] = 0.f;
    for (int d = lane; d < DDIM; d += 32) {
        float xv = xr[d];
#pragma unroll
        for (int e = 0; e < NEXP; e++) acc[e] += xv * wsh[e*DDIM + d];
    }
#pragma unroll
    for (int e = 0; e < NEXP; e++) {
#pragma unroll
        for (int off = 16; off; off >>= 1)
            acc[e] += __shfl_xor_sync(0xffffffffu, acc[e], off);
    }
    if (lane == 0) {
        float l0 = -1e30f; int i0 = 0;
#pragma unroll
        for (int e = 0; e < NEXP; e++) if (acc[e] > l0) { l0 = acc[e]; i0 = e; }
        float l1 = -1e30f; int i1 = 0;
#pragma unroll
        for (int e = 0; e < NEXP; e++) if (e != i0 && acc[e] > l1) { l1 = acc[e]; i1 = e; }
        float r  = expf(l1 - l0);
        float g0 = 1.f / (1.f + r);
        g_eid[n]        = i0;
        g_eid[NTOK + n] = i1;
        g_gv[n]         = g0;
        g_gv[NTOK + n]  = 1.f - g0;
    }
}

// ---------------- GShard positions (block 0; zeroes sync counters) + w1 convert ----------
__global__ void pos_kernel(const float* __restrict__ w1) {
    if (blockIdx.x > 0) {
        conv_units(w1, g_w1h, GATE_CONV + (blockIdx.x - 1) * 4, 4, threadIdx.x, 1024);
        return;
    }
    __shared__ int cnt[1024][NEXP];
    int t = threadIdx.x;
    if (t < NEXP) g_cnt[t] = 0;
    if (t == NEXP) g_convcnt = 0;
    int base = t * 16;
#pragma unroll
    for (int e = 0; e < NEXP; e++) cnt[t][e] = 0;
    for (int j = 0; j < 16; j++) cnt[t][g_eid[base + j]]++;
    __syncthreads();
    if (t < 256) {
        int w = t >> 5, lane = t & 31;
        int s = 0;
        for (int j = 0; j < 32; j++) s += cnt[lane*32 + j][w];
        int incl = s;
#pragma unroll
        for (int off = 1; off < 32; off <<= 1) {
            int v = __shfl_up_sync(0xffffffffu, incl, off);
            if (lane >= off) incl += v;
        }
        int run = incl - s;
        for (int j = 0; j < 32; j++) {
            int v = cnt[lane*32 + j][w];
            cnt[lane*32 + j][w] = run;
            run += v;
        }
    }
    __syncthreads();
    for (int j = 0; j < 16; j++) {
        int i = base + j;
        int e = g_eid[i];
        int p = cnt[t][e]++;
        if (p < CAP) {
            g_pos[i] = p;
        } else {
            g_pos[i] = -1;
            g_gv[i]  = 0.f;
        }
    }
}

// ---------------- dispatch scatter (f32 -> fp16) ----------------
__global__ void dispatch_kernel(const float* __restrict__ x) {
    int i = blockIdx.x;
    int p = g_pos[i];
    if (p < 0) return;
    int e = g_eid[i];
    int n = i & (NTOK - 1);
    const float4 v = ((const float4*)(x + (size_t)n * DDIM))[threadIdx.x];
    __half2* dst = (__half2*)(g_disp + (size_t)(e*CAP + p) * DDIM) + threadIdx.x * 2;
    dst[0] = __floats2half2_rn(v.x, v.y);
    dst[1] = __floats2half2_rn(v.z, v.w);
}

// ---------------- GEMM tile body (device function) ----------------
// CTA 128x128, BK=64, 3-stage cp.async, 8 warps (4m x 2n), warp tile 32x64.
template<int KDIM, int NDIM, bool DO_GELU, typename OutT>
__device__ __forceinline__ void gemm_tile(const __half* __restrict__ A,
                                          const __half* __restrict__ B,
                                          const float* __restrict__ bias,
                                          OutT* __restrict__ C,
                                          int tid, uint32_t sbase) {
    int lane = tid & 31, warp = tid >> 5;
    constexpr int KT = KDIM / 64;
    int wm = (warp >> 1) * 32;
    int wn = (warp & 1) * 64;
    int r8 = lane & 7, t4 = lane >> 3;

    float acc[2][8][4];
#pragma unroll
    for (int mi = 0; mi < 2; mi++)
#pragma unroll
        for (int ni = 0; ni < 8; ni++)
#pragma unroll
            for (int q = 0; q < 4; q++) acc[mi][ni][q] = 0.f;

    auto load_stage = [&](int kt) {
        uint32_t sa = sbase + (uint32_t)(kt % STAGES) * STAGE_BYTES;
        uint32_t sb = sa + 16384;
        const __half* Ap = A + kt * 64;
        const __half* Bp = B + (size_t)(kt * 64) * NDIM;
#pragma unroll
        for (int i = 0; i < 4; i++) {
            int idx = i * 256 + tid;
            int row = idx >> 3, c = idx & 7;
            cpasync16(sa + (uint32_t)(row * 128 + ((c ^ (row & 7)) << 4)),
                      Ap + (size_t)row * KDIM + c * 8);
        }
#pragma unroll
        for (int i = 0; i < 4; i++) {
            int idx = i * 256 + tid;
            int row = idx >> 4, c = idx & 15;
            cpasync16(sb + (uint32_t)(row * 256 + ((c ^ (row & 7)) << 4)),
                      Bp + (size_t)row * NDIM + c * 8);
        }
    };

#pragma unroll
    for (int kt = 0; kt < STAGES - 1; kt++) { load_stage(kt); cp_commit(); }

    for (int kt = 0; kt < KT; kt++) {
        cp_wait<STAGES - 2>();
        __syncthreads();

        int ktp = kt + STAGES - 1;
        if (ktp < KT) load_stage(ktp);
        cp_commit();

        uint32_t sA = sbase + (uint32_t)(kt % STAGES) * STAGE_BYTES;
        uint32_t sB = sA + 16384;
#pragma unroll
        for (int ks4 = 0; ks4 < 4; ks4++) {
            int kc = ks4 * 2;
            uint32_t a[2][4], b[8][2];
#pragma unroll
            for (int mi = 0; mi < 2; mi++) {
                int row = wm + mi * 16 + (t4 & 1) * 8 + r8;
                int cc  = kc + (t4 >> 1);
                ldsm4(a[mi], sA + (uint32_t)(row * 128 + ((cc ^ (row & 7)) << 4)));
            }
#pragma unroll
            for (int nj = 0; nj < 4; nj++) {
                int krow = ks4 * 16 + (lane & 15);
                int c    = ((wn + nj * 16) >> 3) + (lane >> 4);
                uint32_t q[4];
                ldsm4t(q, sB + (uint32_t)(krow * 256 + ((c ^ (krow & 7)) << 4)));
                b[2*nj][0]   = q[0]; b[2*nj][1]   = q[1];
                b[2*nj+1][0] = q[2]; b[2*nj+1][1] = q[3];
            }
#pragma unroll
            for (int mi = 0; mi < 2; mi++)
#pragma unroll
                for (int ni = 0; ni < 8; ni++)
                    mma16816(acc[mi][ni], a[mi], b[ni]);
        }
    }

    int grp = lane >> 2, tig = lane & 3;
#pragma unroll
    for (int mi = 0; mi < 2; mi++) {
#pragma unroll
        for (int ni = 0; ni < 8; ni++) {
            int row = wm + mi * 16 + grp;
            int col = wn + ni * 8 + tig * 2;
            float b0  = bias[col];
            float b1v = bias[col + 1];
            float v0 = acc[mi][ni][0] + b0;
            float v1 = acc[mi][ni][1] + b1v;
            float v2 = acc[mi][ni][2] + b0;
            float v3 = acc[mi][ni][3] + b1v;
            if (DO_GELU) {
                v0 = gelu_exact(v0); v1 = gelu_exact(v1);
                v2 = gelu_exact(v2); v3 = gelu_exact(v3);
            }
            if (sizeof(OutT) == 2) {
                *(__half2*)((__half*)C + (size_t)row * NDIM + col) = __floats2half2_rn(v0, v1);
                *(__half2*)((__half*)C + (size_t)(row + 8) * NDIM + col) = __floats2half2_rn(v2, v3);
            } else {
                *(float2*)((float*)C + (size_t)row * NDIM + col) = make_float2(v0, v1);
                *(float2*)((float*)C + (size_t)(row + 8) * NDIM + col) = make_float2(v2, v3);
            }
        }
    }
}

// ---------------- fused: [w2 conv | gemm1 expert-major | gemm2 expert-major] ----------------
__global__ void __launch_bounds__(256, 2)
fused_kernel(const __half* __restrict__ disp, const __half* __restrict__ w1h,
             const float* __restrict__ b1,   __half* __restrict__ hbuf,
             const float* __restrict__ w2,   __half* __restrict__ w2h,
             const float* __restrict__ b2,   float* __restrict__ ybuf) {
    extern __shared__ char dynsm[];
    int tid = threadIdx.x;
    int bid = blockIdx.x;

    if (bid < CONV_UNITS) {                       // w2 fp16 conversion
        conv_units(w2, w2h, bid, 1, tid, 256);
        __threadfence();
        __syncthreads();
        if (tid == 0) atomicAdd(&g_convcnt, 1);
        return;
    }
    bid -= CONV_UNITS;

    uint32_t sbase = (s2u(dynsm) + 1023u) & ~1023u;

    if (bid < G1_BLOCKS) {                        // gemm1: h = GELU(disp @ w1 + b1)
        int e = bid >> 9, t = bid & 511;
        int bm = (t >> 5) * 128, bn = (t & 31) * 128;
        gemm_tile<DDIM, HDIM, true, __half>(
            disp + (size_t)e * CAP * DDIM + (size_t)bm * DDIM,
            w1h  + (size_t)e * DDIM * HDIM + bn,
            b1   + (size_t)e * HDIM + bn,
            hbuf + (size_t)e * CAP * HDIM + (size_t)bm * HDIM + bn,
            tid, sbase);
        __threadfence();
        __syncthreads();
        if (tid == 0) atomicAdd(&g_cnt[e], 1);
        return;
    }
    bid -= G1_BLOCKS;

    // gemm2: y = h @ w2 + b2 — wait for this expert's gemm1 tiles + w2 conversion
    int e = bid >> 7, t = bid & 127;
    int bm = (t >> 3) * 128, bn = (t & 7) * 128;
    if (tid == 0) {
        while (*(volatile int*)&g_convcnt < CONV_UNITS) __nanosleep(200);
        while (*(volatile int*)&g_cnt[e] < G1_TILES_PER_E) __nanosleep(200);
        __threadfence();
    }
    __syncthreads();
    gemm_tile<HDIM, DDIM, false, float>(
        hbuf + (size_t)e * CAP * HDIM + (size_t)bm * HDIM,
        w2h  + (size_t)e * HDIM * DDIM + bn,
        b2   + (size_t)e * DDIM + bn,
        ybuf + (size_t)e * CAP * DDIM + (size_t)bm * DDIM + bn,
        tid, sbase);
}

// ---------------- combine (gather + gate-weighted sum) ----------------
__global__ void combine_kernel(float* __restrict__ out) {
    int n = blockIdx.x;
    int t = threadIdx.x;
    float4 acc = make_float4(0.f, 0.f, 0.f, 0.f);
#pragma unroll
    for (int kk = 0; kk < 2; kk++) {
        int i = kk * NTOK + n;
        int p = g_pos[i];
        if (p >= 0) {
            float g = g_gv[i];
            const float4 v = *((const float4*)(g_y + (size_t)(g_eid[i]*CAP + p) * DDIM) + t);
            acc.x += g * v.x; acc.y += g * v.y;
            acc.z += g * v.z; acc.w += g * v.w;
        }
    }
    ((float4*)out)[(size_t)n * 256 + t] = acc;
}

// ---------------- launch ----------------
extern "C" void kernel_launch(void* const* d_in, const int* in_sizes, int n_in,
                              void* d_out, int out_size) {
    const float* x  = (const float*)d_in[0];
    const float* wg = (const float*)d_in[1];
    const float* w1 = (const float*)d_in[2];
    const float* b1 = (const float*)d_in[3];
    const float* w2 = (const float*)d_in[4];
    const float* b2 = (const float*)d_in[5];
    float* out = (float*)d_out;

    static int attr_done = 0;
    if (!attr_done) {
        cudaFuncSetAttribute(fused_kernel,
                             cudaFuncAttributeMaxDynamicSharedMemorySize, DSMEM_BYTES);
        attr_done = 1;
    }

    __half* w1h;  cudaGetSymbolAddress((void**)&w1h,  g_w1h);
    __half* w2h;  cudaGetSymbolAddress((void**)&w2h,  g_w2h);
    __half* disp; cudaGetSymbolAddress((void**)&disp, g_disp);
    __half* hbuf; cudaGetSymbolAddress((void**)&hbuf, g_h);
    float*  ybuf; cudaGetSymbolAddress((void**)&ybuf, g_y);

    gate_kernel<<<NTOK/8 + GATE_CONV, 256>>>(x, wg, w1);
    pos_kernel<<<1 + POS_CONV_BLOCKS, 1024>>>(w1);
    dispatch_kernel<<<NENT, 256>>>(x);
    fused_kernel<<<FUSED_BLOCKS, 256, DSMEM_BYTES>>>(
        disp, w1h, b1, hbuf, w2, w2h, b2, ybuf);
    combine_kernel<<<NTOK, 256>>>(out);
}

// round 16
// speedup vs baseline: 1.0540x; 1.0027x over previous
#include <cuda_runtime.h>
#include <cuda_fp16.h>
#include <math.h>
#include <stdint.h>

#define NTOK 8192
#define DDIM 1024
#define HDIM 4096
#define NEXP 8
#define CAP  2048
#define NENT (2*NTOK)

#define STAGES 3
#define STAGE_BYTES 32768          // A 16KB (128m x 64k) + B 16KB (64k x 128n), fp16
#define DSMEM_BYTES (STAGES*STAGE_BYTES + 1024)

#define CONV_UNITS 512
#define WELEMS ((size_t)NEXP*DDIM*HDIM)
#define WQUADS (WELEMS/4)                    // 8,388,608 float4
#define QPB    (WQUADS/CONV_UNITS)           // 16384 float4 per unit
#define GATE_CONV 256
#define POS_CONV_BLOCKS 64                   // 1024-thread blocks, 4 units each

#define G1_TILES_PER_E 512                   // (HDIM/128)*(CAP/128) = 32*16
#define G2_TILES_PER_E 128                   // (DDIM/128)*(CAP/128) = 8*16
#define G1_BLOCKS (NEXP*G1_TILES_PER_E)      // 4096
#define G2_BLOCKS (NEXP*G2_TILES_PER_E)      // 1024
#define FUSED_BLOCKS (CONV_UNITS + G1_BLOCKS + G2_BLOCKS)   // 5632
#define NCNT (NEXP*16)                       // per-(expert, m-block) counters

// ---------------- scratch (device globals; no allocation allowed) ----------------
__device__ __half g_disp[(size_t)NEXP*CAP*DDIM];   // 32 MB
__device__ __half g_h[(size_t)NEXP*CAP*HDIM];      // 128 MB
__device__ float  g_y[(size_t)NEXP*CAP*DDIM];      // 64 MB
__device__ __half g_w1h[WELEMS];                   // 64 MB
__device__ __half g_w2h[WELEMS];                   // 64 MB
__device__ int    g_eid[NENT];
__device__ float  g_gv[NENT];
__device__ int    g_pos[NENT];
__device__ int    g_cnt[NCNT];                     // gemm1 tiles done per (e, m-block)
__device__ int    g_convcnt;                       // w2 conv units done

// ---------------- helpers ----------------
__device__ __forceinline__ uint32_t s2u(const void* p) {
    uint32_t a;
    asm("{ .reg .u64 t; cvta.to.shared.u64 t, %1; cvt.u32.u64 %0, t; }" : "=r"(a) : "l"(p));
    return a;
}
__device__ __forceinline__ void cpasync16(uint32_t dst, const void* src) {
    asm volatile("cp.async.cg.shared.global [%0], [%1], 16;" :: "r"(dst), "l"(src));
}
__device__ __forceinline__ void cp_commit() { asm volatile("cp.async.commit_group;" ::: "memory"); }
template<int N> __device__ __forceinline__ void cp_wait() {
    asm volatile("cp.async.wait_group %0;" :: "n"(N) : "memory");
}
__device__ __forceinline__ void ldsm4(uint32_t* d, uint32_t addr) {
    asm volatile("ldmatrix.sync.aligned.m8n8.x4.shared.b16 {%0,%1,%2,%3}, [%4];"
        : "=r"(d[0]), "=r"(d[1]), "=r"(d[2]), "=r"(d[3]) : "r"(addr));
}
__device__ __forceinline__ void ldsm4t(uint32_t* d, uint32_t addr) {
    asm volatile("ldmatrix.sync.aligned.m8n8.x4.trans.shared.b16 {%0,%1,%2,%3}, [%4];"
        : "=r"(d[0]), "=r"(d[1]), "=r"(d[2]), "=r"(d[3]) : "r"(addr));
}
__device__ __forceinline__ void mma16816(float* d, const uint32_t* a, const uint32_t* b) {
    asm volatile(
        "mma.sync.aligned.m16n8k16.row.col.f32.f16.f16.f32 "
        "{%0,%1,%2,%3}, {%4,%5,%6,%7}, {%8,%9}, {%0,%1,%2,%3};"
        : "+f"(d[0]), "+f"(d[1]), "+f"(d[2]), "+f"(d[3])
        : "r"(a[0]), "r"(a[1]), "r"(a[2]), "r"(a[3]), "r"(b[0]), "r"(b[1]));
}
__device__ __forceinline__ float gelu_exact(float v) {
    return 0.5f * v * (1.f + erff(v * 0.70710678118654752f));
}
__device__ __forceinline__ void conv_units(const float* __restrict__ W,
                                           __half* __restrict__ Wh,
                                           int u0, int units, int tid, int nthr) {
    size_t base = (size_t)u0 * QPB;
    size_t count = (size_t)units * QPB;
    for (size_t j = tid; j < count; j += nthr) {
        size_t i = base + j;
        const float4 v = ((const float4*)W)[i];
        __half2* o = (__half2*)Wh + i * 2;
        o[0] = __floats2half2_rn(v.x, v.y);
        o[1] = __floats2half2_rn(v.z, v.w);
    }
}

// ---------------- gate (+ w1 convert units [0,GATE_CONV)) ----------------
__global__ void gate_kernel(const float* __restrict__ x, const float* __restrict__ wg,
                            const float* __restrict__ w1) {
    if (blockIdx.x >= NTOK/8) {
        conv_units(w1, g_w1h, blockIdx.x - NTOK/8, 1, threadIdx.x, 256);
        return;
    }
    __shared__ float wsh[NEXP*DDIM];
    int tid = threadIdx.x;
    for (int i = tid; i < NEXP*DDIM; i += 256) {
        int d = i / NEXP, e = i % NEXP;
        wsh[e*DDIM + d] = wg[i];
    }
    __syncthreads();
    int warp = tid >> 5, lane = tid & 31;
    int n = blockIdx.x * 8 + warp;
    const float* xr = x + (size_t)n * DDIM;
    float acc[NEXP];
#pragma unroll
    for (int e = 0; e < NEXP; e++) acc[e] = 0.f;
    for (int d = lane; d < DDIM; d += 32) {
        float xv = xr[d];
#pragma unroll
        for (int e = 0; e < NEXP; e++) acc[e] += xv * wsh[e*DDIM + d];
    }
#pragma unroll
    for (int e = 0; e < NEXP; e++) {
#pragma unroll
        for (int off = 16; off; off >>= 1)
            acc[e] += __shfl_xor_sync(0xffffffffu, acc[e], off);
    }
    if (lane == 0) {
        float l0 = -1e30f; int i0 = 0;
#pragma unroll
        for (int e = 0; e < NEXP; e++) if (acc[e] > l0) { l0 = acc[e]; i0 = e; }
        float l1 = -1e30f; int i1 = 0;
#pragma unroll
        for (int e = 0; e < NEXP; e++) if (e != i0 && acc[e] > l1) { l1 = acc[e]; i1 = e; }
        float r  = expf(l1 - l0);
        float g0 = 1.f / (1.f + r);
        g_eid[n]        = i0;
        g_eid[NTOK + n] = i1;
        g_gv[n]         = g0;
        g_gv[NTOK + n]  = 1.f - g0;
    }
}

// ---------------- GShard positions (block 0; zeroes sync counters) + w1 convert ----------
__global__ void pos_kernel(const float* __restrict__ w1) {
    if (blockIdx.x > 0) {
        conv_units(w1, g_w1h, GATE_CONV + (blockIdx.x - 1) * 4, 4, threadIdx.x, 1024);
        return;
    }
    __shared__ int cnt[1024][NEXP];
    int t = threadIdx.x;
    if (t < NCNT) g_cnt[t] = 0;
    if (t == NCNT) g_convcnt = 0;
    int base = t * 16;
#pragma unroll
    for (int e = 0; e < NEXP; e++) cnt[t][e] = 0;
    for (int j = 0; j < 16; j++) cnt[t][g_eid[base + j]]++;
    __syncthreads();
    if (t < 256) {
        int w = t >> 5, lane = t & 31;
        int s = 0;
        for (int j = 0; j < 32; j++) s += cnt[lane*32 + j][w];
        int incl = s;
#pragma unroll
        for (int off = 1; off < 32; off <<= 1) {
            int v = __shfl_up_sync(0xffffffffu, incl, off);
            if (lane >= off) incl += v;
        }
        int run = incl - s;
        for (int j = 0; j < 32; j++) {
            int v = cnt[lane*32 + j][w];
            cnt[lane*32 + j][w] = run;
            run += v;
        }
    }
    __syncthreads();
    for (int j = 0; j < 16; j++) {
        int i = base + j;
        int e = g_eid[i];
        int p = cnt[t][e]++;
        if (p < CAP) {
            g_pos[i] = p;
        } else {
            g_pos[i] = -1;
            g_gv[i]  = 0.f;
        }
    }
}

// ---------------- dispatch scatter (f32 -> fp16) ----------------
__global__ void dispatch_kernel(const float* __restrict__ x) {
    int i = blockIdx.x;
    int p = g_pos[i];
    if (p < 0) return;
    int e = g_eid[i];
    int n = i & (NTOK - 1);
    const float4 v = ((const float4*)(x + (size_t)n * DDIM))[threadIdx.x];
    __half2* dst = (__half2*)(g_disp + (size_t)(e*CAP + p) * DDIM) + threadIdx.x * 2;
    dst[0] = __floats2half2_rn(v.x, v.y);
    dst[1] = __floats2half2_rn(v.z, v.w);
}

// ---------------- GEMM tile body (device function) ----------------
// CTA 128x128, BK=64, 3-stage cp.async, 8 warps (4m x 2n), warp tile 32x64.
template<int KDIM, int NDIM, bool DO_GELU, typename OutT>
__device__ __forceinline__ void gemm_tile(const __half* __restrict__ A,
                                          const __half* __restrict__ B,
                                          const float* __restrict__ bias,
                                          OutT* __restrict__ C,
                                          int tid, uint32_t sbase) {
    int lane = tid & 31, warp = tid >> 5;
    constexpr int KT = KDIM / 64;
    int wm = (warp >> 1) * 32;
    int wn = (warp & 1) * 64;
    int r8 = lane & 7, t4 = lane >> 3;

    float acc[2][8][4];
#pragma unroll
    for (int mi = 0; mi < 2; mi++)
#pragma unroll
        for (int ni = 0; ni < 8; ni++)
#pragma unroll
            for (int q = 0; q < 4; q++) acc[mi][ni][q] = 0.f;

    auto load_stage = [&](int kt) {
        uint32_t sa = sbase + (uint32_t)(kt % STAGES) * STAGE_BYTES;
        uint32_t sb = sa + 16384;
        const __half* Ap = A + kt * 64;
        const __half* Bp = B + (size_t)(kt * 64) * NDIM;
#pragma unroll
        for (int i = 0; i < 4; i++) {
            int idx = i * 256 + tid;
            int row = idx >> 3, c = idx & 7;
            cpasync16(sa + (uint32_t)(row * 128 + ((c ^ (row & 7)) << 4)),
                      Ap + (size_t)row * KDIM + c * 8);
        }
#pragma unroll
        for (int i = 0; i < 4; i++) {
            int idx = i * 256 + tid;
            int row = idx >> 4, c = idx & 15;
            cpasync16(sb + (uint32_t)(row * 256 + ((c ^ (row & 7)) << 4)),
                      Bp + (size_t)row * NDIM + c * 8);
        }
    };

#pragma unroll
    for (int kt = 0; kt < STAGES - 1; kt++) { load_stage(kt); cp_commit(); }

    for (int kt = 0; kt < KT; kt++) {
        cp_wait<STAGES - 2>();
        __syncthreads();

        int ktp = kt + STAGES - 1;
        if (ktp < KT) load_stage(ktp);
        cp_commit();

        uint32_t sA = sbase + (uint32_t)(kt % STAGES) * STAGE_BYTES;
        uint32_t sB = sA + 16384;
#pragma unroll
        for (int ks4 = 0; ks4 < 4; ks4++) {
            int kc = ks4 * 2;
            uint32_t a[2][4], b[8][2];
#pragma unroll
            for (int mi = 0; mi < 2; mi++) {
                int row = wm + mi * 16 + (t4 & 1) * 8 + r8;
                int cc  = kc + (t4 >> 1);
                ldsm4(a[mi], sA + (uint32_t)(row * 128 + ((cc ^ (row & 7)) << 4)));
            }
#pragma unroll
            for (int nj = 0; nj < 4; nj++) {
                int krow = ks4 * 16 + (lane & 15);
                int c    = ((wn + nj * 16) >> 3) + (lane >> 4);
                uint32_t q[4];
                ldsm4t(q, sB + (uint32_t)(krow * 256 + ((c ^ (krow & 7)) << 4)));
                b[2*nj][0]   = q[0]; b[2*nj][1]   = q[1];
                b[2*nj+1][0] = q[2]; b[2*nj+1][1] = q[3];
            }
#pragma unroll
            for (int mi = 0; mi < 2; mi++)
#pragma unroll
                for (int ni = 0; ni < 8; ni++)
                    mma16816(acc[mi][ni], a[mi], b[ni]);
        }
    }

    int grp = lane >> 2, tig = lane & 3;
#pragma unroll
    for (int mi = 0; mi < 2; mi++) {
#pragma unroll
        for (int ni = 0; ni < 8; ni++) {
            int row = wm + mi * 16 + grp;
            int col = wn + ni * 8 + tig * 2;
            float b0  = bias[col];
            float b1v = bias[col + 1];
            float v0 = acc[mi][ni][0] + b0;
            float v1 = acc[mi][ni][1] + b1v;
            float v2 = acc[mi][ni][2] + b0;
            float v3 = acc[mi][ni][3] + b1v;
            if (DO_GELU) {
                v0 = gelu_exact(v0); v1 = gelu_exact(v1);
                v2 = gelu_exact(v2); v3 = gelu_exact(v3);
            }
            if (sizeof(OutT) == 2) {
                *(__half2*)((__half*)C + (size_t)row * NDIM + col) = __floats2half2_rn(v0, v1);
                *(__half2*)((__half*)C + (size_t)(row + 8) * NDIM + col) = __floats2half2_rn(v2, v3);
            } else {
                *(float2*)((float*)C + (size_t)row * NDIM + col) = make_float2(v0, v1);
                *(float2*)((float*)C + (size_t)(row + 8) * NDIM + col) = make_float2(v2, v3);
            }
        }
    }
}

// ---------------- fused: [w2 conv | gemm1 | gemm2], row-block-granular deps ----------------
// gemm1 block t (per expert): bm = (t>>5)*128 (m-group), bn = (t&31)*128.
// The 32 tiles of one (e, m-group) are contiguous in dispatch order.
// gemm2 tile (e, bm) waits only on cnt[e*16 + bm>>7] == 32 (+ w2 conversion).
__global__ void __launch_bounds__(256, 2)
fused_kernel(const __half* __restrict__ disp, const __half* __restrict__ w1h,
             const float* __restrict__ b1,   __half* __restrict__ hbuf,
             const float* __restrict__ w2,   __half* __restrict__ w2h,
             const float* __restrict__ b2,   float* __restrict__ ybuf) {
    extern __shared__ char dynsm[];
    int tid = threadIdx.x;
    int bid = blockIdx.x;

    if (bid < CONV_UNITS) {                       // w2 fp16 conversion
        conv_units(w2, w2h, bid, 1, tid, 256);
        __threadfence();
        __syncthreads();
        if (tid == 0) atomicAdd(&g_convcnt, 1);
        return;
    }
    bid -= CONV_UNITS;

    uint32_t sbase = (s2u(dynsm) + 1023u) & ~1023u;

    if (bid < G1_BLOCKS) {                        // gemm1: h = GELU(disp @ w1 + b1)
        int e = bid >> 9, t = bid & 511;
        int mg = t >> 5;                          // m-group 0..15
        int bm = mg * 128, bn = (t & 31) * 128;
        gemm_tile<DDIM, HDIM, true, __half>(
            disp + (size_t)e * CAP * DDIM + (size_t)bm * DDIM,
            w1h  + (size_t)e * DDIM * HDIM + bn,
            b1   + (size_t)e * HDIM + bn,
            hbuf + (size_t)e * CAP * HDIM + (size_t)bm * HDIM + bn,
            tid, sbase);
        __threadfence();
        __syncthreads();
        if (tid == 0) atomicAdd(&g_cnt[e * 16 + mg], 1);
        return;
    }
    bid -= G1_BLOCKS;

    // gemm2: y = h @ w2 + b2 — wait for this (e, m-group)'s gemm1 tiles + w2 conversion
    int e = bid >> 7, t = bid & 127;
    int mg = t >> 3;
    int bm = mg * 128, bn = (t & 7) * 128;
    if (tid == 0) {
        while (*(volatile int*)&g_convcnt < CONV_UNITS) __nanosleep(200);
        while (*(volatile int*)&g_cnt[e * 16 + mg] < 32) __nanosleep(200);
        __threadfence();
    }
    __syncthreads();
    gemm_tile<HDIM, DDIM, false, float>(
        hbuf + (size_t)e * CAP * HDIM + (size_t)bm * HDIM,
        w2h  + (size_t)e * HDIM * DDIM + bn,
        b2   + (size_t)e * DDIM + bn,
        ybuf + (size_t)e * CAP * DDIM + (size_t)bm * DDIM + bn,
        tid, sbase);
}

// ---------------- combine (gather + gate-weighted sum) ----------------
__global__ void combine_kernel(float* __restrict__ out) {
    int n = blockIdx.x;
    int t = threadIdx.x;
    float4 acc = make_float4(0.f, 0.f, 0.f, 0.f);
#pragma unroll
    for (int kk = 0; kk < 2; kk++) {
        int i = kk * NTOK + n;
        int p = g_pos[i];
        if (p >= 0) {
            float g = g_gv[i];
            const float4 v = *((const float4*)(g_y + (size_t)(g_eid[i]*CAP + p) * DDIM) + t);
            acc.x += g * v.x; acc.y += g * v.y;
            acc.z += g * v.z; acc.w += g * v.w;
        }
    }
    ((float4*)out)[(size_t)n * 256 + t] = acc;
}

// ---------------- launch ----------------
extern "C" void kernel_launch(void* const* d_in, const int* in_sizes, int n_in,
                              void* d_out, int out_size) {
    const float* x  = (const float*)d_in[0];
    const float* wg = (const float*)d_in[1];
    const float* w1 = (const float*)d_in[2];
    const float* b1 = (const float*)d_in[3];
    const float* w2 = (const float*)d_in[4];
    const float* b2 = (const float*)d_in[5];
    float* out = (float*)d_out;

    static int attr_done = 0;
    if (!attr_done) {
        cudaFuncSetAttribute(fused_kernel,
                             cudaFuncAttributeMaxDynamicSharedMemorySize, DSMEM_BYTES);
        attr_done = 1;
    }

    __half* w1h;  cudaGetSymbolAddress((void**)&w1h,  g_w1h);
    __half* w2h;  cudaGetSymbolAddress((void**)&w2h,  g_w2h);
    __half* disp; cudaGetSymbolAddress((void**)&disp, g_disp);
    __half* hbuf; cudaGetSymbolAddress((void**)&hbuf, g_h);
    float*  ybuf; cudaGetSymbolAddress((void**)&ybuf, g_y);

    gate_kernel<<<NTOK/8 + GATE_CONV, 256>>>(x, wg, w1);
    pos_kernel<<<1 + POS_CONV_BLOCKS, 1024>>>(w1);
    dispatch_kernel<<<NENT, 256>>>(x);
    fused_kernel<<<FUSED_BLOCKS, 256, DSMEM_BYTES>>>(
        disp, w1h, b1, hbuf, w2, w2h, b2, ybuf);
    combine_kernel<<<NTOK, 256>>>(out);
}